// round 2
// baseline (speedup 1.0000x reference)
#include <cuda_runtime.h>
#include <cuda_bf16.h>
#include <cstdint>

// Problem constants
#define MDIM 16384            // B*H*W = 4*64*64
#define NDIM 16384            // memory bank rows
#define KDIM 512              // channels
#define ALPHA_C 0.1f
#define NU_C 1e-3f

// Tiling
#define MT 128
#define NT 128
#define KT 32                 // bf16 k-chunk per smem stage
#define SROW 40               // padded smem row (bf16 elems): 80B stride -> ldmatrix conflict-free
#define SCPAD 133             // padded score row (floats): gcd(133,32)=1 -> conflict-free row scan
#define BUF_ELEMS (MT * SROW)           // 5120 bf16 per buffer
#define BUF_BYTES (BUF_ELEMS * 2)       // 10240

// Dynamic smem layout:
// [0,20480)       A tiles  [2][128][40] bf16
// [20480,40960)   B tiles  [2][128][40] bf16
// [40960,41472)   m2s      [128] float
// [41472,109568)  scores   [128][133] float   (reused for block reduction)
#define SMEM_BYTES 109568

// Scratch (device globals are the sanctioned scratch mechanism)
__device__ __align__(16) __nv_bfloat16 g_A [MDIM * KDIM];
__device__ __align__(16) __nv_bfloat16 g_Bm[NDIM * KDIM];
__device__ float g_x2[MDIM];
__device__ float g_m2[NDIM];
__device__ float g_part[MDIM / MT];

// ---------------- PTX helpers ----------------
#define CP16(dst, src) \
  asm volatile("cp.async.cg.shared.global [%0], [%1], 16;\n" :: "r"(dst), "l"(src))
#define CP_COMMIT() asm volatile("cp.async.commit_group;\n" ::: "memory")
#define CP_WAIT(n)  asm volatile("cp.async.wait_group %0;\n" :: "n"(n) : "memory")

#define LDSM4(R0, R1, R2, R3, ADDR) \
  asm volatile("ldmatrix.sync.aligned.m8n8.x4.shared.b16 {%0,%1,%2,%3}, [%4];" \
               : "=r"(R0), "=r"(R1), "=r"(R2), "=r"(R3) : "r"(ADDR))

#define MMA16816(C, A, B0, B1) \
  asm volatile("mma.sync.aligned.m16n8k16.row.col.f32.bf16.bf16.f32 " \
               "{%0,%1,%2,%3},{%4,%5,%6,%7},{%8,%9},{%0,%1,%2,%3};" \
               : "+f"((C)[0]), "+f"((C)[1]), "+f"((C)[2]), "+f"((C)[3]) \
               : "r"((A)[0]), "r"((A)[1]), "r"((A)[2]), "r"((A)[3]), \
                 "r"(B0), "r"(B1))

// ---------------- Prep kernels ----------------

// phi_p (4,512,64,64) fp32 -> g_A[(b*4096+hw)][c] bf16 (transpose via smem tile)
__global__ void prep_phi(const float* __restrict__ phi) {
    __shared__ float t[32][33];
    int b = blockIdx.z, c0 = blockIdx.y * 32, h0 = blockIdx.x * 32;
    int tx = threadIdx.x, ty = threadIdx.y;
    const float* p = phi + ((size_t)b * 512 + c0) * 4096 + h0;
#pragma unroll
    for (int i = 0; i < 4; i++)
        t[ty + 8 * i][tx] = p[(size_t)(ty + 8 * i) * 4096 + tx];
    __syncthreads();
#pragma unroll
    for (int i = 0; i < 4; i++) {
        int row = ty + 8 * i;   // h_local
        g_A[((size_t)b * 4096 + h0 + row) * 512 + c0 + tx] = __float2bfloat16(t[tx][row]);
    }
}

// x2[m] = sum_c phi[b][c][hw]^2 (fp32-exact), coalesced over hw
__global__ void prep_x2(const float* __restrict__ phi) {
    int m = blockIdx.x * 256 + threadIdx.x;
    int b = m >> 12, hw = m & 4095;
    const float* p = phi + (size_t)b * 512 * 4096 + hw;
    float s = 0.f;
#pragma unroll 8
    for (int c = 0; c < 512; c++) { float v = p[(size_t)c * 4096]; s = fmaf(v, v, s); }
    g_x2[m] = s;
}

// memory_bank fp32 -> g_Bm bf16 ; m2[n] = row norm^2 (fp32-exact). One warp per row.
__global__ void prep_mem(const float* __restrict__ mem) {
    int row  = (blockIdx.x * 256 + threadIdx.x) >> 5;
    int lane = threadIdx.x & 31;
    const float* p = mem + (size_t)row * 512;
    __nv_bfloat16* q = g_Bm + (size_t)row * 512;
    float s = 0.f;
#pragma unroll
    for (int i = 0; i < 16; i++) {
        float v = p[lane + i * 32];
        q[lane + i * 32] = __float2bfloat16(v);
        s = fmaf(v, v, s);
    }
#pragma unroll
    for (int o = 16; o > 0; o >>= 1) s += __shfl_xor_sync(0xffffffffu, s, o);
    if (lane == 0) g_m2[row] = s;
}

// ---------------- Main fused kernel ----------------

__device__ __forceinline__ void cp_stage(uint32_t aOff, uint32_t bOff, int buf,
                                         int m0, int n0, int k0, int tid) {
#pragma unroll
    for (int i = 0; i < 2; i++) {
        int c = tid + i * 256;       // 0..511 : 128 rows x 4 x 16B segments
        int row = c >> 2, seg = c & 3;
        uint32_t da = aOff + (uint32_t)(buf * BUF_BYTES + (row * SROW + seg * 8) * 2);
        const __nv_bfloat16* sa = g_A + (size_t)(m0 + row) * KDIM + k0 + seg * 8;
        CP16(da, sa);
        uint32_t db = bOff + (uint32_t)(buf * BUF_BYTES + (row * SROW + seg * 8) * 2);
        const __nv_bfloat16* sb = g_Bm + (size_t)(n0 + row) * KDIM + k0 + seg * 8;
        CP16(db, sb);
    }
}

__device__ __forceinline__ void insert6(float v, float& q0, float& q1, float& q2,
                                        float& q3, float& q4, float& q5) {
    if (v < q5) {
        q5 = v;
        if (q5 < q4) { float t = q4; q4 = q5; q5 = t;
            if (q4 < q3) { t = q3; q3 = q4; q4 = t;
                if (q3 < q2) { t = q2; q2 = q3; q3 = t;
                    if (q2 < q1) { t = q1; q1 = q2; q2 = t;
                        if (q1 < q0) { t = q0; q0 = q1; q1 = t; } } } } }
    }
}

__global__ __launch_bounds__(256, 1)
void knn_gemm(const float* __restrict__ rptr) {
    extern __shared__ char smem[];
    float* m2s    = (float*)(smem + 2 * BUF_BYTES * 2);   // offset 40960
    float* scores = (float*)(smem + 2 * BUF_BYTES * 2 + 512);

    const int tid  = threadIdx.x;
    const int lane = tid & 31;
    const int warp = tid >> 5;
    const int wm   = warp & 3;   // 4 warps along M
    const int wn   = warp >> 2;  // 2 warps along N
    const int m0   = blockIdx.x * MT;

    uint32_t sbase = (uint32_t)__cvta_generic_to_shared(smem);
    const uint32_t aOff = sbase;
    const uint32_t bOff = sbase + 2 * BUF_BYTES;

    // ldmatrix per-lane address components
    const int g  = lane >> 2;
    const int q4i = lane & 3;
    const int aRow    = wm * 32 + (lane & 15);
    const int aColSel = ((lane >> 4) & 1) * 8;
    const int bRow    = wn * 64 + (lane & 7) + ((lane >> 4) & 1) * 8;
    const int bColSel = ((lane >> 3) & 1) * 8;

    float x2r = 0.f;
    if (tid < 128) x2r = g_x2[m0 + tid];
    float q0 = INFINITY, q1 = INFINITY, q2 = INFINITY,
          q3 = INFINITY, q4 = INFINITY, q5 = INFINITY;

#pragma unroll 1
    for (int nt = 0; nt < NDIM / NT; nt++) {
        const int n0 = nt * NT;
        if (tid < 128) m2s[tid] = g_m2[n0 + tid];

        float acc[2][8][4];
#pragma unroll
        for (int mi = 0; mi < 2; mi++)
#pragma unroll
            for (int ni = 0; ni < 8; ni++)
#pragma unroll
                for (int r = 0; r < 4; r++) acc[mi][ni][r] = 0.f;

        cp_stage(aOff, bOff, 0, m0, n0, 0, tid);
        CP_COMMIT();

#pragma unroll 1
        for (int ks = 0; ks < KDIM / KT; ks++) {
            if (ks < KDIM / KT - 1) {
                cp_stage(aOff, bOff, (ks + 1) & 1, m0, n0, (ks + 1) * KT, tid);
                CP_COMMIT();
                CP_WAIT(1);
            } else {
                CP_WAIT(0);
            }
            __syncthreads();

            const uint32_t abuf = aOff + (ks & 1) * BUF_BYTES;
            const uint32_t bbuf = bOff + (ks & 1) * BUF_BYTES;
#pragma unroll
            for (int kk = 0; kk < KT; kk += 16) {
                uint32_t a[2][4], bf[8][2];
#pragma unroll
                for (int mi = 0; mi < 2; mi++) {
                    uint32_t ad = abuf + (uint32_t)(((aRow + mi * 16) * SROW + kk + aColSel) * 2);
                    LDSM4(a[mi][0], a[mi][1], a[mi][2], a[mi][3], ad);
                }
#pragma unroll
                for (int jp = 0; jp < 4; jp++) {
                    uint32_t bd = bbuf + (uint32_t)(((bRow + jp * 16) * SROW + kk + bColSel) * 2);
                    LDSM4(bf[2 * jp][0], bf[2 * jp][1], bf[2 * jp + 1][0], bf[2 * jp + 1][1], bd);
                }
#pragma unroll
                for (int mi = 0; mi < 2; mi++)
#pragma unroll
                    for (int ni = 0; ni < 8; ni++)
                        MMA16816(acc[mi][ni], a[mi], bf[ni][0], bf[ni][1]);
            }
            __syncthreads();
        }

        // Epilogue: scores[row][col] = m2[col] - 2*dot   (x2 added in the scan)
#pragma unroll
        for (int mi = 0; mi < 2; mi++) {
            int row0 = wm * 32 + mi * 16 + g;
#pragma unroll
            for (int ni = 0; ni < 8; ni++) {
                int col = wn * 64 + ni * 8 + 2 * q4i;
                float m20 = m2s[col], m21 = m2s[col + 1];
                scores[row0 * SCPAD + col]           = m20 - 2.f * acc[mi][ni][0];
                scores[row0 * SCPAD + col + 1]       = m21 - 2.f * acc[mi][ni][1];
                scores[(row0 + 8) * SCPAD + col]     = m20 - 2.f * acc[mi][ni][2];
                scores[(row0 + 8) * SCPAD + col + 1] = m21 - 2.f * acc[mi][ni][3];
            }
        }
        __syncthreads();

        // Streaming top-6: one thread per query row scans 128 candidates
        if (tid < 128) {
            const float* srow = scores + tid * SCPAD;
#pragma unroll 4
            for (int j = 0; j < NT; j++) {
                float v = fmaxf(x2r + srow[j], 0.f);   // d2 = max(x2+m2-2dot, 0)
                insert6(v, q0, q1, q2, q3, q4, q5);
            }
        }
        __syncthreads();
    }

    // Per-row hinge contributions, then CTA reduction
    float part = 0.f;
    if (tid < 128) {
        float rv = rptr[0];
        float r2 = rv * rv;
        part = fmaxf(q0 - r2, 0.f) + fmaxf(q1 - r2, 0.f) + fmaxf(q2 - r2, 0.f)
             + fmaxf(r2 - q3 - ALPHA_C, 0.f) + fmaxf(r2 - q4 - ALPHA_C, 0.f)
             + fmaxf(r2 - q5 - ALPHA_C, 0.f);
    }
    __syncthreads();
    float* red = scores;           // reuse (>=256 floats)
    red[tid] = part;
    __syncthreads();
#pragma unroll
    for (int o = 128; o > 0; o >>= 1) {
        if (tid < o) red[tid] += red[tid + o];
        __syncthreads();
    }
    if (tid == 0) g_part[blockIdx.x] = red[0];
}

// Deterministic final reduction of 128 CTA partials
__global__ void finalize_loss(float* __restrict__ out) {
    __shared__ float s[128];
    int t = threadIdx.x;
    s[t] = g_part[t];
    __syncthreads();
#pragma unroll
    for (int o = 64; o > 0; o >>= 1) {
        if (t < o) s[t] += s[t + o];
        __syncthreads();
    }
    // (sum_att + sum_rep) / (16384*3) / NU
    if (t == 0) out[0] = s[0] * (1.0f / (49152.0f * NU_C));
}

// ---------------- launch ----------------
extern "C" void kernel_launch(void* const* d_in, const int* in_sizes, int n_in,
                              void* d_out, int out_size) {
    (void)in_sizes; (void)n_in; (void)out_size;
    const float* phi = (const float*)d_in[0];
    const float* mem = (const float*)d_in[1];
    const float* r   = (const float*)d_in[2];
    float* out = (float*)d_out;

    cudaFuncSetAttribute(knn_gemm, cudaFuncAttributeMaxDynamicSharedMemorySize, SMEM_BYTES);

    prep_phi<<<dim3(128, 16, 4), dim3(32, 8)>>>(phi);
    prep_x2<<<MDIM / 256, 256>>>(phi);
    prep_mem<<<NDIM / 8, 256>>>(mem);   // FIX: one warp per row -> NDIM/8 blocks of 8 warps
    knn_gemm<<<MDIM / MT, 256, SMEM_BYTES>>>(r);
    finalize_loss<<<1, 128>>>(out);
}

// round 4
// speedup vs baseline: 1.3761x; 1.3761x over previous
#include <cuda_runtime.h>
#include <cuda_bf16.h>
#include <cstdint>

// Problem constants
#define MDIM 16384
#define NDIM 16384
#define KDIM 512
#define ALPHA_C 0.1f
#define NU_C 1e-3f

// Tiling
#define MT 128
#define NT 128
#define KT 64                 // bf16 k-chunk per smem stage
#define SROW 72               // padded smem row (bf16): 144B stride, LDSM conflict-free
#define SCPAD 133             // padded score row (floats)
#define BUF_ELEMS (MT * SROW)            // 9216
#define BUF_BYTES (BUF_ELEMS * 2)        // 18432
#define NTILES (NDIM / NT)               // 128

// smem layout (bytes)
// [0, 36864)        A stages [2][128][72] bf16
// [36864, 73728)    B stages [2][128][72] bf16
// [73728, 74752)    m2s [2][128] float
// [74752, 142848)   scores [128][133] float (reused: merge staging, reduction)
#define SM_A 0
#define SM_B 36864
#define SM_M2 73728
#define SM_SC 74752
#define SMEM_BYTES 142848

// Scratch
__device__ __align__(16) __nv_bfloat16 g_A [MDIM * KDIM];
__device__ __align__(16) __nv_bfloat16 g_Bm[NDIM * KDIM];
__device__ float g_x2[MDIM];
__device__ float g_m2[NDIM];
__device__ float g_part[MDIM / MT];

// ---------------- PTX helpers ----------------
#define CP16(dst, src) \
  asm volatile("cp.async.cg.shared.global [%0], [%1], 16;\n" :: "r"(dst), "l"(src))
#define CP_COMMIT() asm volatile("cp.async.commit_group;\n" ::: "memory")
#define CP_WAIT(n)  asm volatile("cp.async.wait_group %0;\n" :: "n"(n) : "memory")

#define LDSM4(R0, R1, R2, R3, ADDR) \
  asm volatile("ldmatrix.sync.aligned.m8n8.x4.shared.b16 {%0,%1,%2,%3}, [%4];" \
               : "=r"(R0), "=r"(R1), "=r"(R2), "=r"(R3) : "r"(ADDR))

#define MMA16816(C, A, B0, B1) \
  asm volatile("mma.sync.aligned.m16n8k16.row.col.f32.bf16.bf16.f32 " \
               "{%0,%1,%2,%3},{%4,%5,%6,%7},{%8,%9},{%0,%1,%2,%3};" \
               : "+f"((C)[0]), "+f"((C)[1]), "+f"((C)[2]), "+f"((C)[3]) \
               : "r"((A)[0]), "r"((A)[1]), "r"((A)[2]), "r"((A)[3]), \
                 "r"(B0), "r"(B1))

// ---------------- Prep kernels ----------------
__global__ void prep_phi(const float* __restrict__ phi) {
    __shared__ float t[32][33];
    int b = blockIdx.z, c0 = blockIdx.y * 32, h0 = blockIdx.x * 32;
    int tx = threadIdx.x, ty = threadIdx.y;
    const float* p = phi + ((size_t)b * 512 + c0) * 4096 + h0;
#pragma unroll
    for (int i = 0; i < 4; i++)
        t[ty + 8 * i][tx] = p[(size_t)(ty + 8 * i) * 4096 + tx];
    __syncthreads();
#pragma unroll
    for (int i = 0; i < 4; i++) {
        int row = ty + 8 * i;
        g_A[((size_t)b * 4096 + h0 + row) * 512 + c0 + tx] = __float2bfloat16(t[tx][row]);
    }
}

__global__ void prep_x2(const float* __restrict__ phi) {
    int m = blockIdx.x * 256 + threadIdx.x;
    int b = m >> 12, hw = m & 4095;
    const float* p = phi + (size_t)b * 512 * 4096 + hw;
    float s = 0.f;
#pragma unroll 8
    for (int c = 0; c < 512; c++) { float v = p[(size_t)c * 4096]; s = fmaf(v, v, s); }
    g_x2[m] = s;
}

__global__ void prep_mem(const float* __restrict__ mem) {
    int row  = (blockIdx.x * 256 + threadIdx.x) >> 5;
    int lane = threadIdx.x & 31;
    const float* p = mem + (size_t)row * 512;
    __nv_bfloat16* q = g_Bm + (size_t)row * 512;
    float s = 0.f;
#pragma unroll
    for (int i = 0; i < 16; i++) {
        float v = p[lane + i * 32];
        q[lane + i * 32] = __float2bfloat16(v);
        s = fmaf(v, v, s);
    }
#pragma unroll
    for (int o = 16; o > 0; o >>= 1) s += __shfl_xor_sync(0xffffffffu, s, o);
    if (lane == 0) g_m2[row] = s;
}

// ---------------- Main fused kernel ----------------
__device__ __forceinline__ void cp_stage(uint32_t aOff, uint32_t bOff, int buf,
                                         int m0, int n0, int k0, int tid) {
    // 128 rows x 8 segs(16B) per matrix = 1024 chunks; 512 threads -> 2 each
#pragma unroll
    for (int i = 0; i < 2; i++) {
        int c = tid + i * 512;
        int row = c >> 3, seg = c & 7;
        uint32_t off = (uint32_t)(buf * BUF_BYTES + (row * SROW + seg * 8) * 2);
        CP16(aOff + off, g_A  + (size_t)(m0 + row) * KDIM + k0 + seg * 8);
        CP16(bOff + off, g_Bm + (size_t)(n0 + row) * KDIM + k0 + seg * 8);
    }
}

__device__ __forceinline__ void insert6(float v, float& q0, float& q1, float& q2,
                                        float& q3, float& q4, float& q5) {
    if (v < q5) {
        q5 = v;
        if (q5 < q4) { float t = q4; q4 = q5; q5 = t;
            if (q4 < q3) { t = q3; q3 = q4; q4 = t;
                if (q3 < q2) { t = q2; q2 = q3; q3 = t;
                    if (q2 < q1) { t = q1; q1 = q2; q2 = t;
                        if (q1 < q0) { t = q0; q0 = q1; q1 = t; } } } } }
    }
}

__global__ __launch_bounds__(512, 1)
void knn_gemm(const float* __restrict__ rptr) {
    extern __shared__ char smem[];
    float* m2s    = (float*)(smem + SM_M2);
    float* scores = (float*)(smem + SM_SC);

    const int tid  = threadIdx.x;
    const int lane = tid & 31;
    const int warp = tid >> 5;
    const int wm   = warp & 3;    // 4 warps along M (32 rows each)
    const int wn   = warp >> 2;   // 4 warps along N (32 cols each)
    const int m0   = blockIdx.x * MT;

    uint32_t sbase = (uint32_t)__cvta_generic_to_shared(smem);
    const uint32_t aOff = sbase + SM_A;
    const uint32_t bOff = sbase + SM_B;

    // ldmatrix lane mappings (identical pattern to the verified R2 kernel)
    const int g       = lane >> 2;
    const int aRow    = wm * 32 + (lane & 15);
    const int aColSel = ((lane >> 4) & 1) * 8;
    const int bRow    = wn * 32 + (lane & 7) + ((lane >> 4) & 1) * 8;
    const int bColSel = ((lane >> 3) & 1) * 8;

    // scan assignment: 4 threads per row, 32 cols each
    const int srowi = tid >> 2;
    const int cg    = tid & 3;
    const float x2r = g_x2[m0 + srowi];

    float q0 = INFINITY, q1 = INFINITY, q2 = INFINITY,
          q3 = INFINITY, q4 = INFINITY, q5 = INFINITY;

#pragma unroll 1
    for (int nt = 0; nt < NTILES; nt++) {
        const int n0 = nt * NT;
        const int mb = nt & 1;
        if (tid < 128) m2s[mb * 128 + tid] = g_m2[n0 + tid];

        float acc[2][4][4];
#pragma unroll
        for (int mi = 0; mi < 2; mi++)
#pragma unroll
            for (int ni = 0; ni < 4; ni++)
#pragma unroll
                for (int r = 0; r < 4; r++) acc[mi][ni][r] = 0.f;

        cp_stage(aOff, bOff, 0, m0, n0, 0, tid);
        CP_COMMIT();

#pragma unroll 1
        for (int ks = 0; ks < KDIM / KT; ks++) {
            if (ks < KDIM / KT - 1) {
                cp_stage(aOff, bOff, (ks + 1) & 1, m0, n0, (ks + 1) * KT, tid);
                CP_COMMIT();
                CP_WAIT(1);
            } else {
                CP_WAIT(0);
            }
            __syncthreads();

            const uint32_t abuf = aOff + (ks & 1) * BUF_BYTES;
            const uint32_t bbuf = bOff + (ks & 1) * BUF_BYTES;
#pragma unroll
            for (int kk = 0; kk < KT; kk += 16) {
                uint32_t a[2][4], bf[4][2];
#pragma unroll
                for (int mi = 0; mi < 2; mi++) {
                    uint32_t ad = abuf + (uint32_t)(((aRow + mi * 16) * SROW + kk + aColSel) * 2);
                    LDSM4(a[mi][0], a[mi][1], a[mi][2], a[mi][3], ad);
                }
#pragma unroll
                for (int jp = 0; jp < 2; jp++) {
                    uint32_t bd = bbuf + (uint32_t)(((bRow + jp * 16) * SROW + kk + bColSel) * 2);
                    LDSM4(bf[2 * jp][0], bf[2 * jp][1], bf[2 * jp + 1][0], bf[2 * jp + 1][1], bd);
                }
#pragma unroll
                for (int mi = 0; mi < 2; mi++)
#pragma unroll
                    for (int ni = 0; ni < 4; ni++)
                        MMA16816(acc[mi][ni], a[mi], bf[ni][0], bf[ni][1]);
            }
            __syncthreads();
        }

        // Epilogue: scores[row][col] = m2[col] - 2*dot
#pragma unroll
        for (int mi = 0; mi < 2; mi++) {
            int row0 = wm * 32 + mi * 16 + g;
#pragma unroll
            for (int ni = 0; ni < 4; ni++) {
                int col = wn * 32 + ni * 8 + 2 * (lane & 3);
                float m20 = m2s[mb * 128 + col], m21 = m2s[mb * 128 + col + 1];
                scores[row0 * SCPAD + col]           = fmaf(-2.f, acc[mi][ni][0], m20);
                scores[row0 * SCPAD + col + 1]       = fmaf(-2.f, acc[mi][ni][1], m21);
                scores[(row0 + 8) * SCPAD + col]     = fmaf(-2.f, acc[mi][ni][2], m20);
                scores[(row0 + 8) * SCPAD + col + 1] = fmaf(-2.f, acc[mi][ni][3], m21);
            }
        }
        __syncthreads();

        // All 512 threads scan: thread (row srowi, col group cg) handles 32 cols,
        // rotated start keeps the warp's 32 lanes on distinct banks each step.
        {
            const float* srow = scores + srowi * SCPAD + cg * 32;
            const int rot = cg * 8;
#pragma unroll 8
            for (int j = 0; j < 32; j++) {
                int jj = (j + rot) & 31;
                float v = fmaxf(x2r + srow[jj], 0.f);
                insert6(v, q0, q1, q2, q3, q4, q5);
            }
        }
        __syncthreads();
    }

    // Merge the 4 partial top-6 sets per row
    {
        float* stage = scores;
        int base = srowi * 24 + cg * 6;
        stage[base + 0] = q0; stage[base + 1] = q1; stage[base + 2] = q2;
        stage[base + 3] = q3; stage[base + 4] = q4; stage[base + 5] = q5;
    }
    __syncthreads();

    float part = 0.f;
    if (tid < 128) {
        float f0 = INFINITY, f1 = INFINITY, f2 = INFINITY,
              f3 = INFINITY, f4 = INFINITY, f5 = INFINITY;
        const float* stage = scores + tid * 24;
#pragma unroll
        for (int i = 0; i < 24; i++) insert6(stage[i], f0, f1, f2, f3, f4, f5);
        float rv = rptr[0];
        float r2 = rv * rv;
        part = fmaxf(f0 - r2, 0.f) + fmaxf(f1 - r2, 0.f) + fmaxf(f2 - r2, 0.f)
             + fmaxf(r2 - f3 - ALPHA_C, 0.f) + fmaxf(r2 - f4 - ALPHA_C, 0.f)
             + fmaxf(r2 - f5 - ALPHA_C, 0.f);
    }
    __syncthreads();
    float* red = scores;
    red[tid] = part;
    __syncthreads();
#pragma unroll
    for (int o = 256; o > 0; o >>= 1) {
        if (tid < o) red[tid] += red[tid + o];
        __syncthreads();
    }
    if (tid == 0) g_part[blockIdx.x] = red[0];
}

// Deterministic final reduction
__global__ void finalize_loss(float* __restrict__ out) {
    __shared__ float s[128];
    int t = threadIdx.x;
    s[t] = g_part[t];
    __syncthreads();
#pragma unroll
    for (int o = 64; o > 0; o >>= 1) {
        if (t < o) s[t] += s[t + o];
        __syncthreads();
    }
    if (t == 0) out[0] = s[0] * (1.0f / (49152.0f * NU_C));
}

// ---------------- launch ----------------
extern "C" void kernel_launch(void* const* d_in, const int* in_sizes, int n_in,
                              void* d_out, int out_size) {
    (void)in_sizes; (void)n_in; (void)out_size;
    const float* phi = (const float*)d_in[0];
    const float* mem = (const float*)d_in[1];
    const float* r   = (const float*)d_in[2];
    float* out = (float*)d_out;

    cudaFuncSetAttribute(knn_gemm, cudaFuncAttributeMaxDynamicSharedMemorySize, SMEM_BYTES);

    prep_phi<<<dim3(128, 16, 4), dim3(32, 8)>>>(phi);
    prep_x2<<<MDIM / 256, 256>>>(phi);
    prep_mem<<<NDIM / 8, 256>>>(mem);
    knn_gemm<<<MDIM / MT, 512, SMEM_BYTES>>>(r);
    finalize_loss<<<1, 128>>>(out);
}

// round 7
// speedup vs baseline: 1.6020x; 1.1642x over previous
#include <cuda_runtime.h>
#include <cuda_bf16.h>
#include <cstdint>

// Problem constants
#define MDIM 16384
#define NDIM 16384
#define KDIM 512
#define ALPHA_C 0.1f
#define NU_C 1e-3f

#define MT 128
#define NT 128
#define NTILES (NDIM / NT)          // 128
#define NSTAGES (NTILES * 8)        // 1024 k-stages of 64 across all tiles
#define SCPAD 129                   // scores row pad (floats)

// smem layout (bytes)
#define SM_A   0                    // 8 chunks x [128 x 128B] SW128   = 131072
#define SM_B   131072               // 3-slot ring x [128 x 128B] SW128 = 49152
#define SM_M2  180224               // 2 x 128 floats
#define SM_SC  181248               // 64 x 129 floats = 33024 (also reduce scratch)
#define SMEM_BYTES 214272

// Scratch
__device__ __align__(16) __nv_bfloat16 g_A [MDIM * KDIM];
__device__ __align__(16) __nv_bfloat16 g_Bm[NDIM * KDIM];
__device__ float g_x2[MDIM];
__device__ float g_m2[NDIM];
__device__ float g_part[MDIM / MT];

// ---------------- PTX helpers ----------------
#define CP16(dst, src) \
  asm volatile("cp.async.cg.shared.global [%0], [%1], 16;\n" :: "r"(dst), "l"(src))
#define CP_COMMIT() asm volatile("cp.async.commit_group;\n" ::: "memory")
#define CP_WAIT(n)  asm volatile("cp.async.wait_group %0;\n" :: "n"(n) : "memory")

#define LDSM4(R0, R1, R2, R3, ADDR) \
  asm volatile("ldmatrix.sync.aligned.m8n8.x4.shared.b16 {%0,%1,%2,%3}, [%4];" \
               : "=r"(R0), "=r"(R1), "=r"(R2), "=r"(R3) : "r"(ADDR))

#define MMA16816(C, A, B0, B1) \
  asm volatile("mma.sync.aligned.m16n8k16.row.col.f32.bf16.bf16.f32 " \
               "{%0,%1,%2,%3},{%4,%5,%6,%7},{%8,%9},{%0,%1,%2,%3};" \
               : "+f"((C)[0]), "+f"((C)[1]), "+f"((C)[2]), "+f"((C)[3]) \
               : "r"((A)[0]), "r"((A)[1]), "r"((A)[2]), "r"((A)[3]), \
                 "r"(B0), "r"(B1))

#define SWZ128(x) ((x) ^ (((x) >> 3) & 0x70))

// ---------------- Prep kernels ----------------
__global__ void prep_phi(const float* __restrict__ phi) {
    __shared__ float t[32][33];
    int b = blockIdx.z, c0 = blockIdx.y * 32, h0 = blockIdx.x * 32;
    int tx = threadIdx.x, ty = threadIdx.y;
    const float* p = phi + ((size_t)b * 512 + c0) * 4096 + h0;
#pragma unroll
    for (int i = 0; i < 4; i++)
        t[ty + 8 * i][tx] = p[(size_t)(ty + 8 * i) * 4096 + tx];
    __syncthreads();
#pragma unroll
    for (int i = 0; i < 4; i++) {
        int row = ty + 8 * i;
        g_A[((size_t)b * 4096 + h0 + row) * 512 + c0 + tx] = __float2bfloat16(t[tx][row]);
    }
}

__global__ void prep_x2(const float* __restrict__ phi) {
    int m = blockIdx.x * 256 + threadIdx.x;
    int b = m >> 12, hw = m & 4095;
    const float* p = phi + (size_t)b * 512 * 4096 + hw;
    float s = 0.f;
#pragma unroll 8
    for (int c = 0; c < 512; c++) { float v = p[(size_t)c * 4096]; s = fmaf(v, v, s); }
    g_x2[m] = s;
}

__global__ void prep_mem(const float* __restrict__ mem) {
    int row  = (blockIdx.x * 256 + threadIdx.x) >> 5;
    int lane = threadIdx.x & 31;
    const float* p = mem + (size_t)row * 512;
    __nv_bfloat16* q = g_Bm + (size_t)row * 512;
    float s = 0.f;
#pragma unroll
    for (int i = 0; i < 16; i++) {
        float v = p[lane + i * 32];
        q[lane + i * 32] = __float2bfloat16(v);
        s = fmaf(v, v, s);
    }
#pragma unroll
    for (int o = 16; o > 0; o >>= 1) s += __shfl_xor_sync(0xffffffffu, s, o);
    if (lane == 0) g_m2[row] = s;
}

// ---------------- Main fused kernel ----------------
__device__ __forceinline__ void insert6(float v, float& q0, float& q1, float& q2,
                                        float& q3, float& q4, float& q5) {
    if (v < q5) {
        q5 = v;
        if (q5 < q4) { float t = q4; q4 = q5; q5 = t;
            if (q4 < q3) { t = q3; q3 = q4; q4 = t;
                if (q3 < q2) { t = q2; q2 = q3; q3 = t;
                    if (q2 < q1) { t = q1; q1 = q2; q2 = t;
                        if (q1 < q0) { t = q0; q0 = q1; q1 = t; } } } } }
    }
}

__device__ __forceinline__ void b_stage(uint32_t bOff, int slot, int n0, int s, int tid) {
#pragma unroll
    for (int i = 0; i < 2; i++) {
        int c = tid + i * 512;                // 1024 16B-units: 128 rows x 8 segs
        int row = c >> 3, seg = c & 7;
        uint32_t dst = bOff + (uint32_t)(slot * 16384 + SWZ128(row * 128 + seg * 16));
        CP16(dst, g_Bm + (size_t)(n0 + row) * KDIM + s * 64 + seg * 8);
    }
}

__global__ __launch_bounds__(512, 1)
void knn_gemm(const float* __restrict__ rptr) {
    extern __shared__ char smem[];
    float* m2s    = (float*)(smem + SM_M2);
    float* scores = (float*)(smem + SM_SC);

    const int tid  = threadIdx.x;
    const int lane = tid & 31;
    const int warp = tid >> 5;
    const int wm   = warp & 3;     // 4 warps along M
    const int wn   = warp >> 2;    // 4 warps along N
    const int m0   = blockIdx.x * MT;

    uint32_t sbase = (uint32_t)__cvta_generic_to_shared(smem);
    const uint32_t aOff = sbase + SM_A;
    const uint32_t bOff = sbase + SM_B;

    // ldmatrix lane mappings (verified in R2/R4)
    const int aRow    = wm * 32 + (lane & 15);
    const int aColSel = ((lane >> 4) & 1) * 8;
    const int bRow    = wn * 32 + (lane & 7) + ((lane >> 4) & 1) * 8;
    const int bColSel = ((lane >> 3) & 1) * 8;

    // epilogue scan: 8 threads/row, 16 cols each, two passes of 64 rows
    const int myrow = tid >> 3;       // 0..63
    const int r8    = tid & 7;
    const float x2a = g_x2[m0 + myrow];
    const float x2b = g_x2[m0 + 64 + myrow];

    // ---- resident A load: 8 chunks x [128 rows x 128B] SW128 (FULL K=512)
    {
#pragma unroll
        for (int i = 0; i < 16; i++) {
            int c = tid + i * 512;            // 8192 16B units = 8 chunks x 128 rows x 8 segs
            int chunk = c >> 10, u = c & 1023;
            int row = u >> 3, seg = u & 7;
            uint32_t dst = aOff + (uint32_t)(chunk * 16384 + SWZ128(row * 128 + seg * 16));
            CP16(dst, g_A + (size_t)(m0 + row) * KDIM + chunk * 64 + seg * 8);
        }
        CP_COMMIT();
    }
    // ---- B ring prologue: stages 0, 1
    b_stage(bOff, 0, 0, 0, tid); CP_COMMIT();
    b_stage(bOff, 1, 0, 1, tid); CP_COMMIT();

    float q0 = INFINITY, q1 = INFINITY, q2 = INFINITY,
          q3 = INFINITY, q4 = INFINITY, q5 = INFINITY;
    float u0 = INFINITY, u1 = INFINITY, u2 = INFINITY,
          u3 = INFINITY, u4 = INFINITY, u5 = INFINITY;

    float acc[2][4][4];
#pragma unroll
    for (int mi = 0; mi < 2; mi++)
#pragma unroll
        for (int ni = 0; ni < 4; ni++)
#pragma unroll
            for (int r = 0; r < 4; r++) acc[mi][ni][r] = 0.f;

    int slot = 0;
#pragma unroll 1
    for (int g = 0; g < NSTAGES; g++) {
        const int s  = g & 7;
        const int nt = g >> 3;
        const int mb = nt & 1;

        if (s == 0 && tid < 128) m2s[mb * 128 + tid] = g_m2[nt * NT + tid];

        CP_WAIT(1);
        __syncthreads();

        // compute stage: B ring slot, A chunk == s (k = s*64 + kk)
        const uint32_t bbuf = bOff + slot * 16384;
        const uint32_t abuf = aOff + s * 16384;
#pragma unroll
        for (int kk = 0; kk < 64; kk += 16) {
            uint32_t a[2][4], bf[4][2];
#pragma unroll
            for (int mi = 0; mi < 2; mi++) {
                uint32_t ad = abuf + (uint32_t)SWZ128(((aRow + mi * 16) * 128 + (kk + aColSel) * 2));
                LDSM4(a[mi][0], a[mi][1], a[mi][2], a[mi][3], ad);
            }
#pragma unroll
            for (int jp = 0; jp < 2; jp++) {
                uint32_t bd = bbuf + (uint32_t)SWZ128(((bRow + jp * 16) * 128 + (kk + bColSel) * 2));
                LDSM4(bf[2 * jp][0], bf[2 * jp][1], bf[2 * jp + 1][0], bf[2 * jp + 1][1], bd);
            }
#pragma unroll
            for (int mi = 0; mi < 2; mi++)
#pragma unroll
                for (int ni = 0; ni < 4; ni++)
                    MMA16816(acc[mi][ni], a[mi], bf[ni][0], bf[ni][1]);
        }

        // keep the ring rolling (prefetch continues through epilogue)
        const int g2 = g + 2;
        if (g2 < NSTAGES) {
            const int slot2 = (slot + 2 >= 3) ? slot - 1 : slot + 2;
            b_stage(bOff, slot2, (g2 >> 3) * NT, g2 & 7, tid);
        }
        CP_COMMIT();
        if (++slot == 3) slot = 0;

        if (s == 7) {
            // ===== epilogue for tile nt: two passes of 64 rows =====
#pragma unroll
            for (int pass = 0; pass < 2; pass++) {
                __syncthreads();   // previous scan readers done / MMA writers aligned
                if ((wm >> 1) == pass) {
#pragma unroll
                    for (int mi = 0; mi < 2; mi++) {
                        int lrow = (wm & 1) * 32 + mi * 16 + (lane >> 2);
#pragma unroll
                        for (int ni = 0; ni < 4; ni++) {
                            int col = wn * 32 + ni * 8 + 2 * (lane & 3);
                            float m20 = m2s[mb * 128 + col], m21 = m2s[mb * 128 + col + 1];
                            scores[lrow * SCPAD + col]           = fmaf(-2.f, acc[mi][ni][0], m20);
                            scores[lrow * SCPAD + col + 1]       = fmaf(-2.f, acc[mi][ni][1], m21);
                            scores[(lrow + 8) * SCPAD + col]     = fmaf(-2.f, acc[mi][ni][2], m20);
                            scores[(lrow + 8) * SCPAD + col + 1] = fmaf(-2.f, acc[mi][ni][3], m21);
                        }
                    }
                }
                __syncthreads();
                // all 512 threads scan: row myrow (local), 16 cols, rotated
                {
                    const float* srow = scores + myrow * SCPAD + r8 * 16;
                    const float x2v = pass ? x2b : x2a;
#pragma unroll
                    for (int j = 0; j < 16; j++) {
                        int jj = (j + 2 * r8) & 15;
                        float v = fmaxf(x2v + srow[jj], 0.f);
                        if (pass == 0) insert6(v, q0, q1, q2, q3, q4, q5);
                        else           insert6(v, u0, u1, u2, u3, u4, u5);
                    }
                }
            }
            __syncthreads();
            // zero acc for next tile
#pragma unroll
            for (int mi = 0; mi < 2; mi++)
#pragma unroll
                for (int ni = 0; ni < 4; ni++)
#pragma unroll
                    for (int r = 0; r < 4; r++) acc[mi][ni][r] = 0.f;
        }
    }

    // ---- merge 8 partial top-6 per row via intra-warp shuffles (width 8)
    // FIX: snapshot all 6 partner values BEFORE any insert (partner lists mutate in lockstep)
#pragma unroll
    for (int off = 4; off > 0; off >>= 1) {
        float t0 = __shfl_down_sync(0xffffffffu, q0, off, 8);
        float t1 = __shfl_down_sync(0xffffffffu, q1, off, 8);
        float t2 = __shfl_down_sync(0xffffffffu, q2, off, 8);
        float t3 = __shfl_down_sync(0xffffffffu, q3, off, 8);
        float t4 = __shfl_down_sync(0xffffffffu, q4, off, 8);
        float t5 = __shfl_down_sync(0xffffffffu, q5, off, 8);
        float s0 = __shfl_down_sync(0xffffffffu, u0, off, 8);
        float s1 = __shfl_down_sync(0xffffffffu, u1, off, 8);
        float s2 = __shfl_down_sync(0xffffffffu, u2, off, 8);
        float s3 = __shfl_down_sync(0xffffffffu, u3, off, 8);
        float s4 = __shfl_down_sync(0xffffffffu, u4, off, 8);
        float s5 = __shfl_down_sync(0xffffffffu, u5, off, 8);
        insert6(t0, q0, q1, q2, q3, q4, q5);
        insert6(t1, q0, q1, q2, q3, q4, q5);
        insert6(t2, q0, q1, q2, q3, q4, q5);
        insert6(t3, q0, q1, q2, q3, q4, q5);
        insert6(t4, q0, q1, q2, q3, q4, q5);
        insert6(t5, q0, q1, q2, q3, q4, q5);
        insert6(s0, u0, u1, u2, u3, u4, u5);
        insert6(s1, u0, u1, u2, u3, u4, u5);
        insert6(s2, u0, u1, u2, u3, u4, u5);
        insert6(s3, u0, u1, u2, u3, u4, u5);
        insert6(s4, u0, u1, u2, u3, u4, u5);
        insert6(s5, u0, u1, u2, u3, u4, u5);
    }

    float part = 0.f;
    if (r8 == 0) {
        float rv = rptr[0];
        float r2 = rv * rv;
        part  = fmaxf(q0 - r2, 0.f) + fmaxf(q1 - r2, 0.f) + fmaxf(q2 - r2, 0.f)
              + fmaxf(r2 - q3 - ALPHA_C, 0.f) + fmaxf(r2 - q4 - ALPHA_C, 0.f)
              + fmaxf(r2 - q5 - ALPHA_C, 0.f);
        part += fmaxf(u0 - r2, 0.f) + fmaxf(u1 - r2, 0.f) + fmaxf(u2 - r2, 0.f)
              + fmaxf(r2 - u3 - ALPHA_C, 0.f) + fmaxf(r2 - u4 - ALPHA_C, 0.f)
              + fmaxf(r2 - u5 - ALPHA_C, 0.f);
    }
    __syncthreads();
    float* red = scores;
    red[tid] = part;
    __syncthreads();
#pragma unroll
    for (int o = 256; o > 0; o >>= 1) {
        if (tid < o) red[tid] += red[tid + o];
        __syncthreads();
    }
    if (tid == 0) g_part[blockIdx.x] = red[0];
}

// Deterministic final reduction
__global__ void finalize_loss(float* __restrict__ out) {
    __shared__ float s[128];
    int t = threadIdx.x;
    s[t] = g_part[t];
    __syncthreads();
#pragma unroll
    for (int o = 64; o > 0; o >>= 1) {
        if (t < o) s[t] += s[t + o];
        __syncthreads();
    }
    if (t == 0) out[0] = s[0] * (1.0f / (49152.0f * NU_C));
}

// ---------------- launch ----------------
extern "C" void kernel_launch(void* const* d_in, const int* in_sizes, int n_in,
                              void* d_out, int out_size) {
    (void)in_sizes; (void)n_in; (void)out_size;
    const float* phi = (const float*)d_in[0];
    const float* mem = (const float*)d_in[1];
    const float* r   = (const float*)d_in[2];
    float* out = (float*)d_out;

    cudaFuncSetAttribute(knn_gemm, cudaFuncAttributeMaxDynamicSharedMemorySize, SMEM_BYTES);

    prep_phi<<<dim3(128, 16, 4), dim3(32, 8)>>>(phi);
    prep_x2<<<MDIM / 256, 256>>>(phi);
    prep_mem<<<NDIM / 8, 256>>>(mem);
    knn_gemm<<<MDIM / MT, 512, SMEM_BYTES>>>(r);
    finalize_loss<<<1, 128>>>(out);
}

// round 8
// speedup vs baseline: 1.8228x; 1.1378x over previous
#include <cuda_runtime.h>
#include <cuda_bf16.h>
#include <cstdint>

// Problem constants
#define MDIM 16384
#define NDIM 16384
#define KDIM 512
#define ALPHA_C 0.1f
#define NU_C 1e-3f

#define MT 128
#define NT 128
#define NTILES (NDIM / NT)          // 128
#define NSTAGES (NTILES * 8)        // 1024 k-stages of 64

// smem layout (bytes)
#define SM_A   0                    // 8 chunks x [128 x 128B] SW128 = 131072
#define SM_B   131072               // 4-slot ring x 16384 = 65536
#define SM_M2  196608               // 2 x 128 floats = 1024
#define SM_STG 197632               // 128 rows x 24 floats = 12288 (also reduce scratch)
#define SMEM_BYTES 209920

// Scratch
__device__ __align__(16) __nv_bfloat16 g_A [MDIM * KDIM];
__device__ __align__(16) __nv_bfloat16 g_Bm[NDIM * KDIM];
__device__ float g_x2[MDIM];
__device__ float g_m2[NDIM];
__device__ float g_part[MDIM / MT];

// ---------------- PTX helpers ----------------
#define CP16(dst, src) \
  asm volatile("cp.async.cg.shared.global [%0], [%1], 16;\n" :: "r"(dst), "l"(src))
#define CP_COMMIT() asm volatile("cp.async.commit_group;\n" ::: "memory")
#define CP_WAIT(n)  asm volatile("cp.async.wait_group %0;\n" :: "n"(n) : "memory")

#define LDSM4(R0, R1, R2, R3, ADDR) \
  asm volatile("ldmatrix.sync.aligned.m8n8.x4.shared.b16 {%0,%1,%2,%3}, [%4];" \
               : "=r"(R0), "=r"(R1), "=r"(R2), "=r"(R3) : "r"(ADDR))

#define MMA16816(C, A, B0, B1) \
  asm volatile("mma.sync.aligned.m16n8k16.row.col.f32.bf16.bf16.f32 " \
               "{%0,%1,%2,%3},{%4,%5,%6,%7},{%8,%9},{%0,%1,%2,%3};" \
               : "+f"((C)[0]), "+f"((C)[1]), "+f"((C)[2]), "+f"((C)[3]) \
               : "r"((A)[0]), "r"((A)[1]), "r"((A)[2]), "r"((A)[3]), \
                 "r"(B0), "r"(B1))

#define SWZ128(x) ((x) ^ (((x) >> 3) & 0x70))

// ---------------- Prep kernels ----------------
__global__ void prep_phi(const float* __restrict__ phi) {
    __shared__ float t[32][33];
    int b = blockIdx.z, c0 = blockIdx.y * 32, h0 = blockIdx.x * 32;
    int tx = threadIdx.x, ty = threadIdx.y;
    const float* p = phi + ((size_t)b * 512 + c0) * 4096 + h0;
#pragma unroll
    for (int i = 0; i < 4; i++)
        t[ty + 8 * i][tx] = p[(size_t)(ty + 8 * i) * 4096 + tx];
    __syncthreads();
#pragma unroll
    for (int i = 0; i < 4; i++) {
        int row = ty + 8 * i;
        g_A[((size_t)b * 4096 + h0 + row) * 512 + c0 + tx] = __float2bfloat16(t[tx][row]);
    }
}

__global__ void prep_x2(const float* __restrict__ phi) {
    int m = blockIdx.x * 256 + threadIdx.x;
    int b = m >> 12, hw = m & 4095;
    const float* p = phi + (size_t)b * 512 * 4096 + hw;
    float s = 0.f;
#pragma unroll 8
    for (int c = 0; c < 512; c++) { float v = p[(size_t)c * 4096]; s = fmaf(v, v, s); }
    g_x2[m] = s;
}

__global__ void prep_mem(const float* __restrict__ mem) {
    int row  = (blockIdx.x * 256 + threadIdx.x) >> 5;
    int lane = threadIdx.x & 31;
    const float* p = mem + (size_t)row * 512;
    __nv_bfloat16* q = g_Bm + (size_t)row * 512;
    float s = 0.f;
#pragma unroll
    for (int i = 0; i < 16; i++) {
        float v = p[lane + i * 32];
        q[lane + i * 32] = __float2bfloat16(v);
        s = fmaf(v, v, s);
    }
#pragma unroll
    for (int o = 16; o > 0; o >>= 1) s += __shfl_xor_sync(0xffffffffu, s, o);
    if (lane == 0) g_m2[row] = s;
}

// ---------------- Main fused kernel ----------------
__device__ __forceinline__ void insert6a(float v, float (&q)[6]) {
    if (v < q[5]) {
        q[5] = v;
        if (q[5] < q[4]) { float t = q[4]; q[4] = q[5]; q[5] = t;
            if (q[4] < q[3]) { t = q[3]; q[3] = q[4]; q[4] = t;
                if (q[3] < q[2]) { t = q[2]; q[2] = q[3]; q[3] = t;
                    if (q[2] < q[1]) { t = q[1]; q[1] = q[2]; q[2] = t;
                        if (q[1] < q[0]) { t = q[0]; q[0] = q[1]; q[1] = t; } } } } }
    }
}

__device__ __forceinline__ void b_stage(uint32_t bOff, int slot, int n0, int s, int tid) {
#pragma unroll
    for (int i = 0; i < 2; i++) {
        int c = tid + i * 512;                // 1024 16B-units: 128 rows x 8 segs
        int row = c >> 3, seg = c & 7;
        uint32_t dst = bOff + (uint32_t)(slot * 16384 + SWZ128(row * 128 + seg * 16));
        CP16(dst, g_Bm + (size_t)(n0 + row) * KDIM + s * 64 + seg * 8);
    }
}

__global__ __launch_bounds__(512, 1)
void knn_gemm(const float* __restrict__ rptr) {
    extern __shared__ char smem[];
    float* m2s   = (float*)(smem + SM_M2);
    float* stage = (float*)(smem + SM_STG);

    const int tid  = threadIdx.x;
    const int lane = tid & 31;
    const int warp = tid >> 5;
    const int wm   = warp & 3;     // 4 warps along M
    const int wn   = warp >> 2;    // 4 warps along N
    const int m0   = blockIdx.x * MT;

    uint32_t sbase = (uint32_t)__cvta_generic_to_shared(smem);
    const uint32_t aOff = sbase + SM_A;
    const uint32_t bOff = sbase + SM_B;

    // ldmatrix lane mappings (verified R2/R4/R7)
    const int aRow    = wm * 32 + (lane & 15);
    const int aColSel = ((lane >> 4) & 1) * 8;
    const int bRow    = wn * 32 + (lane & 7) + ((lane >> 4) & 1) * 8;
    const int bColSel = ((lane >> 3) & 1) * 8;

    const int g  = lane >> 2;      // quad row within 16-row fragment
    const int qd = lane & 3;       // quad column pair

    // x2 for this thread's 4 rows: rows = wm*32 + mi*16 + g + p*8
    float x2v[2][2];
#pragma unroll
    for (int mi = 0; mi < 2; mi++)
#pragma unroll
        for (int p = 0; p < 2; p++)
            x2v[mi][p] = g_x2[m0 + wm * 32 + mi * 16 + g + p * 8];

    // ---- resident A load: 8 chunks x [128 rows x 128B] SW128 (full K)
#pragma unroll
    for (int i = 0; i < 16; i++) {
        int c = tid + i * 512;
        int chunk = c >> 10, u = c & 1023;
        int row = u >> 3, seg = u & 7;
        uint32_t dst = aOff + (uint32_t)(chunk * 16384 + SWZ128(row * 128 + seg * 16));
        CP16(dst, g_A + (size_t)(m0 + row) * KDIM + chunk * 64 + seg * 8);
    }
    CP_COMMIT();
    // ---- B ring prologue: stages 0,1,2 (prefetch distance 3)
    b_stage(bOff, 0, 0, 0, tid); CP_COMMIT();
    b_stage(bOff, 1, 0, 1, tid); CP_COMMIT();
    b_stage(bOff, 2, 0, 2, tid); CP_COMMIT();

    // running top-6 per (mi, p) row
    float ql[2][2][6];
#pragma unroll
    for (int mi = 0; mi < 2; mi++)
#pragma unroll
        for (int p = 0; p < 2; p++)
#pragma unroll
            for (int j = 0; j < 6; j++) ql[mi][p][j] = INFINITY;

    float acc[2][4][4];
#pragma unroll
    for (int mi = 0; mi < 2; mi++)
#pragma unroll
        for (int ni = 0; ni < 4; ni++)
#pragma unroll
            for (int r = 0; r < 4; r++) acc[mi][ni][r] = 0.f;

#pragma unroll 1
    for (int gg = 0; gg < NSTAGES; gg++) {
        const int s  = gg & 7;
        const int nt = gg >> 3;
        const int mb = nt & 1;

        if (s == 0 && tid < 128) m2s[mb * 128 + tid] = g_m2[nt * NT + tid];

        CP_WAIT(2);
        __syncthreads();

        const uint32_t bbuf = bOff + (gg & 3) * 16384;
        const uint32_t abuf = aOff + s * 16384;
#pragma unroll
        for (int kk = 0; kk < 64; kk += 16) {
            uint32_t a[2][4], bf[4][2];
#pragma unroll
            for (int mi = 0; mi < 2; mi++) {
                uint32_t ad = abuf + (uint32_t)SWZ128(((aRow + mi * 16) * 128 + (kk + aColSel) * 2));
                LDSM4(a[mi][0], a[mi][1], a[mi][2], a[mi][3], ad);
            }
#pragma unroll
            for (int jp = 0; jp < 2; jp++) {
                uint32_t bd = bbuf + (uint32_t)SWZ128(((bRow + jp * 16) * 128 + (kk + bColSel) * 2));
                LDSM4(bf[2 * jp][0], bf[2 * jp][1], bf[2 * jp + 1][0], bf[2 * jp + 1][1], bd);
            }
#pragma unroll
            for (int mi = 0; mi < 2; mi++)
#pragma unroll
                for (int ni = 0; ni < 4; ni++)
                    MMA16816(acc[mi][ni], a[mi], bf[ni][0], bf[ni][1]);
        }

        // keep the ring rolling (always commit; group accounting needs it)
        const int g3 = gg + 3;
        if (g3 < NSTAGES) b_stage(bOff, g3 & 3, (g3 >> 3) * NT, g3 & 7, tid);
        CP_COMMIT();

        if (s == 7) {
            // ===== in-register epilogue: insert 16 distances into 4 running lists =====
#pragma unroll
            for (int mi = 0; mi < 2; mi++)
#pragma unroll
                for (int ni = 0; ni < 4; ni++) {
                    const int col = wn * 32 + ni * 8 + 2 * qd;
                    const float m20 = m2s[mb * 128 + col];
                    const float m21 = m2s[mb * 128 + col + 1];
                    insert6a(fmaxf(fmaf(-2.f, acc[mi][ni][0], x2v[mi][0] + m20), 0.f), ql[mi][0]);
                    insert6a(fmaxf(fmaf(-2.f, acc[mi][ni][1], x2v[mi][0] + m21), 0.f), ql[mi][0]);
                    insert6a(fmaxf(fmaf(-2.f, acc[mi][ni][2], x2v[mi][1] + m20), 0.f), ql[mi][1]);
                    insert6a(fmaxf(fmaf(-2.f, acc[mi][ni][3], x2v[mi][1] + m21), 0.f), ql[mi][1]);
                    acc[mi][ni][0] = 0.f; acc[mi][ni][1] = 0.f;
                    acc[mi][ni][2] = 0.f; acc[mi][ni][3] = 0.f;
                }
        }
    }

    // ---- quad merge (lanes of a quad hold the same 4 rows), snapshot-before-insert
#pragma unroll
    for (int off = 2; off > 0; off >>= 1) {
#pragma unroll
        for (int mi = 0; mi < 2; mi++)
#pragma unroll
            for (int p = 0; p < 2; p++) {
                float t[6];
#pragma unroll
                for (int j = 0; j < 6; j++)
                    t[j] = __shfl_down_sync(0xffffffffu, ql[mi][p][j], off, 4);
#pragma unroll
                for (int j = 0; j < 6; j++) insert6a(t[j], ql[mi][p]);
            }
    }

    // ---- cross-warp merge staging: 4 N-warps per row, 6 values each
    if (qd == 0) {
#pragma unroll
        for (int mi = 0; mi < 2; mi++)
#pragma unroll
            for (int p = 0; p < 2; p++) {
                int r = wm * 32 + mi * 16 + g + p * 8;
#pragma unroll
                for (int j = 0; j < 6; j++)
                    stage[r * 24 + wn * 6 + j] = ql[mi][p][j];
            }
    }
    __syncthreads();

    float part = 0.f;
    if (tid < 128) {
        float f[6] = {INFINITY, INFINITY, INFINITY, INFINITY, INFINITY, INFINITY};
        const float* sr = stage + tid * 24;
#pragma unroll
        for (int i = 0; i < 24; i++) insert6a(sr[i], f);
        float rv = rptr[0];
        float r2 = rv * rv;
        part = fmaxf(f[0] - r2, 0.f) + fmaxf(f[1] - r2, 0.f) + fmaxf(f[2] - r2, 0.f)
             + fmaxf(r2 - f[3] - ALPHA_C, 0.f) + fmaxf(r2 - f[4] - ALPHA_C, 0.f)
             + fmaxf(r2 - f[5] - ALPHA_C, 0.f);
    }
    __syncthreads();
    float* red = stage;            // reuse (3072 floats >= 512)
    red[tid] = part;
    __syncthreads();
#pragma unroll
    for (int o = 256; o > 0; o >>= 1) {
        if (tid < o) red[tid] += red[tid + o];
        __syncthreads();
    }
    if (tid == 0) g_part[blockIdx.x] = red[0];
}

// Deterministic final reduction
__global__ void finalize_loss(float* __restrict__ out) {
    __shared__ float s[128];
    int t = threadIdx.x;
    s[t] = g_part[t];
    __syncthreads();
#pragma unroll
    for (int o = 64; o > 0; o >>= 1) {
        if (t < o) s[t] += s[t + o];
        __syncthreads();
    }
    if (t == 0) out[0] = s[0] * (1.0f / (49152.0f * NU_C));
}

// ---------------- launch ----------------
extern "C" void kernel_launch(void* const* d_in, const int* in_sizes, int n_in,
                              void* d_out, int out_size) {
    (void)in_sizes; (void)n_in; (void)out_size;
    const float* phi = (const float*)d_in[0];
    const float* mem = (const float*)d_in[1];
    const float* r   = (const float*)d_in[2];
    float* out = (float*)d_out;

    cudaFuncSetAttribute(knn_gemm, cudaFuncAttributeMaxDynamicSharedMemorySize, SMEM_BYTES);

    prep_phi<<<dim3(128, 16, 4), dim3(32, 8)>>>(phi);
    prep_x2<<<MDIM / 256, 256>>>(phi);
    prep_mem<<<NDIM / 8, 256>>>(mem);
    knn_gemm<<<MDIM / MT, 512, SMEM_BYTES>>>(r);
    finalize_loss<<<1, 128>>>(out);
}